// round 15
// baseline (speedup 1.0000x reference)
#include <cuda_runtime.h>

#define B_TOT    8192
#define T_LEN    512
#define F_IN     24
#define H_DIM    12
#define CHUNK    8
#define EPW      8            // elements per warp
#define WPB      2            // warps per block (independent; no __syncthreads)
#define EPB      (EPW * WPB)  // 16
#define NTHREADS 64
#define NCHUNK   (T_LEN / CHUNK)
#define XS_STRIDE 28          // floats per (tt,elem) x row: e*112B mod 128 all distinct
#define XWARP    (2 * CHUNK * EPW * XS_STRIDE)  // per-warp x floats (dbl buf) = 3584
#define HSTRIDE  20           // floats per elem in h buffer: e*80B mod 128 all distinct
#define HWARP    (2 * EPW * HSTRIDE)            // per-warp h floats (dbl buf) = 320
#define SMEM_BYTES ((WPB * XWARP + WPB * HWARP) * 4)   // 31232 B

typedef unsigned long long u64;

__device__ __forceinline__ unsigned smem_u32(const void* p) {
    return (unsigned)__cvta_generic_to_shared(p);
}
__device__ __forceinline__ void cp_async16(unsigned dst, const void* src) {
    asm volatile("cp.async.cg.shared.global [%0], [%1], 16;\n" :: "r"(dst), "l"(src));
}
__device__ __forceinline__ void cp_commit() {
    asm volatile("cp.async.commit_group;\n" ::: "memory");
}
template <int N> __device__ __forceinline__ void cp_wait() {
    asm volatile("cp.async.wait_group %0;\n" :: "n"(N) : "memory");
}

__device__ __forceinline__ u64 pack2(float lo, float hi) {
    u64 d; asm("mov.b64 %0, {%1, %2};" : "=l"(d) : "f"(lo), "f"(hi)); return d;
}
__device__ __forceinline__ void unpack2(u64 d, float& lo, float& hi) {
    asm("mov.b64 {%0, %1}, %2;" : "=f"(lo), "=f"(hi) : "l"(d));
}
__device__ __forceinline__ u64 fma2(u64 a, u64 b, u64 c) {
    u64 d; asm("fma.rn.f32x2 %0, %1, %2, %3;" : "=l"(d) : "l"(a), "l"(b), "l"(c)); return d;
}
__device__ __forceinline__ float hadd2(u64 a) {
    float lo, hi; unpack2(a, lo, hi); return lo + hi;
}

// h exchange ops: volatile (mutual order preserved: STS of step t precedes
// LDS of step t+1) but NO memory clobber -> independent x-loads / FP code
// may be hoisted across by the compiler to cover the chain latency.
__device__ __forceinline__ void sts128v(unsigned addr, float a, float b, float c, float d) {
    asm volatile("st.shared.v4.f32 [%0], {%1, %2, %3, %4};"
                 :: "r"(addr), "f"(a), "f"(b), "f"(c), "f"(d));
}
__device__ __forceinline__ float4 lds128v(unsigned addr) {
    float4 v;
    asm volatile("ld.shared.v4.f32 {%0, %1, %2, %3}, [%4];"
                 : "=f"(v.x), "=f"(v.y), "=f"(v.z), "=f"(v.w) : "r"(addr));
    return v;
}

// tanh on PRESCALED input: sx = 2*log2(e)*x -> tanh(x) = 1 - 2*rcp(2^sx + 1).
__device__ __forceinline__ float tanh_prescaled(float sx) {
    float e;
    asm("ex2.approx.f32 %0, %1;" : "=f"(e) : "f"(sx));
    float r;
    asm("rcp.approx.f32 %0, %1;" : "=f"(r) : "f"(e + 1.0f));
    return fmaf(-2.0f, r, 1.0f);
}

#define SCALE_T 2.885390082f   // 2*log2(e)

__global__ void __launch_bounds__(NTHREADS) rnn_fused_kernel(
    const float* __restrict__ x,
    const float* __restrict__ W_ih, const float* __restrict__ b_ih,
    const float* __restrict__ W_hh, const float* __restrict__ b_hh,
    const float* __restrict__ W1,   const float* __restrict__ b1,
    const float* __restrict__ W2,   const float* __restrict__ b2,
    const float* __restrict__ W3,   const float* __restrict__ b3,
    float* __restrict__ out)
{
    extern __shared__ float smemf[];
    __shared__ float sW1[144], sW2[144], sb1[12], sb2[12], sW3[12], sb3[1];

    const int tid  = threadIdx.x;
    const int wid  = tid >> 5;
    const int lane = tid & 31;
    const int e    = lane >> 2;       // element within warp (0..7)
    const int sub  = lane & 3;        // 3 h-rows per thread
    const int b    = blockIdx.x * EPB + wid * EPW + e;
    const int j0   = sub * 3;

    float* xw = smemf + wid * XWARP;                  // warp-private x staging
    float* hw = smemf + WPB * XWARP + wid * HWARP;    // warp-private h state

    for (int i = lane; i < 144; i += 32) { sW1[i] = W1[i]; sW2[i] = W2[i]; }
    if (lane < 12) { sb1[lane] = b1[lane]; sb2[lane] = b2[lane]; sW3[lane] = W3[lane]; }
    if (lane == 0) sb3[0] = b3[0];

    // iproj weights packed (prescaled); rec weights scalar (prescaled)
    u64 wih2[3][F_IN / 2], biasp[3];
    float whh[3][H_DIM];
    #pragma unroll
    for (int c = 0; c < 3; c++) {
        const int j = j0 + c;
        #pragma unroll
        for (int p = 0; p < F_IN / 2; p++)
            wih2[c][p] = pack2(SCALE_T * W_ih[j * F_IN + 2 * p],
                               SCALE_T * W_ih[j * F_IN + 2 * p + 1]);
        #pragma unroll
        for (int k = 0; k < H_DIM; k++)
            whh[c][k] = SCALE_T * W_hh[j * H_DIM + k];
        biasp[c] = pack2(SCALE_T * (b_ih[j] + b_hh[j]), 0.0f);
    }

    const unsigned hbase = smem_u32(hw);
    const unsigned hrd_e = hbase + (unsigned)(e * HSTRIDE * 4);
    const unsigned hwr   = hrd_e + (unsigned)(sub * 16);
    sts128v(hwr, 0.0f, 0.0f, 0.0f, 0.0f);   // init h=0 in slot 0
    __syncwarp();

    // cp.async staging: thread (e,sub) loads timesteps {sub, sub+4} of its elem
    const float* src0 = x + ((long)b * T_LEN + sub) * F_IN;
    const unsigned xwb  = smem_u32(xw);
    const unsigned dstL = xwb + (unsigned)(((sub * EPW + e) * XS_STRIDE) * 4);
    const unsigned dstH = xwb + (unsigned)((((sub + 4) * EPW + e) * XS_STRIDE) * 4);

    auto load_chunk = [&](int bufidx, int c) {
        const float* s = src0 + (long)c * (CHUNK * F_IN);
        const unsigned boff = (unsigned)bufidx * (XWARP / 2 * 4);
        #pragma unroll
        for (int q = 0; q < 6; q++) {
            cp_async16(dstL + boff + (unsigned)(q * 16), s + q * 4);
            cp_async16(dstH + boff + (unsigned)(q * 16), s + 4 * F_IN + q * 4);
        }
        cp_commit();
    };

    load_chunk(0, 0);

    for (int c = 0; c < NCHUNK; c++) {
        if (c + 1 < NCHUNK) { load_chunk((c + 1) & 1, c + 1); cp_wait<1>(); }
        else                { cp_wait<0>(); }
        __syncwarp();   // all lanes' chunk-c cp.async data visible warp-wide

        const float* buf = xw + (c & 1) * (XWARP / 2);

        #pragma unroll
        for (int tt = 0; tt < CHUNK; tt++) {
            const unsigned rds = (unsigned)((tt & 1) * (EPW * HSTRIDE * 4));
            const unsigned wrs = (unsigned)(((tt + 1) & 1) * (EPW * HSTRIDE * 4));

            // x row: 6 conflict-free LDS.128, plain loads (freely schedulable)
            const ulonglong2* xr = (const ulonglong2*)(buf + (tt * EPW + e) * XS_STRIDE);
            u64 a0 = biasp[0], a1 = biasp[1], a2 = biasp[2];
            #pragma unroll
            for (int q = 0; q < 6; q++) {
                ulonglong2 v = xr[q];
                a0 = fma2(wih2[0][2 * q + 0], v.x, a0);
                a1 = fma2(wih2[1][2 * q + 0], v.x, a1);
                a2 = fma2(wih2[2][2 * q + 0], v.x, a2);
                a0 = fma2(wih2[0][2 * q + 1], v.y, a0);
                a1 = fma2(wih2[1][2 * q + 1], v.y, a1);
                a2 = fma2(wih2[2][2 * q + 1], v.y, a2);
            }
            const float xp0 = hadd2(a0), xp1 = hadd2(a1), xp2 = hadd2(a2);

            // h: 4 conflict-free LDS.128 (ordered only vs the h STS chain)
            float4 h0 = lds128v(hrd_e + rds);
            float4 h1 = lds128v(hrd_e + rds + 16);
            float4 h2 = lds128v(hrd_e + rds + 32);
            float4 h3 = lds128v(hrd_e + rds + 48);

            float r0, r1, r2;
            {
                float u = fmaf(whh[0][0], h0.x, xp0);
                float v = whh[0][3] * h1.x;
                float w = whh[0][6] * h2.x;
                u = fmaf(whh[0][1], h0.y, u);
                v = fmaf(whh[0][4], h1.y, v);
                w = fmaf(whh[0][7], h2.y, w);
                u = fmaf(whh[0][2], h0.z, u);
                v = fmaf(whh[0][5], h1.z, v);
                w = fmaf(whh[0][8], h2.z, w);
                u = fmaf(whh[0][9], h3.x, u);
                v = fmaf(whh[0][10], h3.y, v);
                w = fmaf(whh[0][11], h3.z, w);
                r0 = (u + v) + w;
            }
            {
                float u = fmaf(whh[1][0], h0.x, xp1);
                float v = whh[1][3] * h1.x;
                float w = whh[1][6] * h2.x;
                u = fmaf(whh[1][1], h0.y, u);
                v = fmaf(whh[1][4], h1.y, v);
                w = fmaf(whh[1][7], h2.y, w);
                u = fmaf(whh[1][2], h0.z, u);
                v = fmaf(whh[1][5], h1.z, v);
                w = fmaf(whh[1][8], h2.z, w);
                u = fmaf(whh[1][9], h3.x, u);
                v = fmaf(whh[1][10], h3.y, v);
                w = fmaf(whh[1][11], h3.z, w);
                r1 = (u + v) + w;
            }
            {
                float u = fmaf(whh[2][0], h0.x, xp2);
                float v = whh[2][3] * h1.x;
                float w = whh[2][6] * h2.x;
                u = fmaf(whh[2][1], h0.y, u);
                v = fmaf(whh[2][4], h1.y, v);
                w = fmaf(whh[2][7], h2.y, w);
                u = fmaf(whh[2][2], h0.z, u);
                v = fmaf(whh[2][5], h1.z, v);
                w = fmaf(whh[2][8], h2.z, w);
                u = fmaf(whh[2][9], h3.x, u);
                v = fmaf(whh[2][10], h3.y, v);
                w = fmaf(whh[2][11], h3.z, w);
                r2 = (u + v) + w;
            }

            const float hl0 = tanh_prescaled(r0);
            const float hl1 = tanh_prescaled(r1);
            const float hl2 = tanh_prescaled(r2);

            // publish: one STS.128 (3 values + pad); converged warp + in-order
            // LSU makes next step's LDS see it; volatile keeps ST/LD order.
            sts128v(hwr + wrs, hl0, hl1, hl2, 0.0f);
        }
    }

    __syncwarp();
    // MLP head: one thread per element; final h in slot (512 & 1) = 0
    if (sub == 0) {
        float h_all[H_DIM];
        #pragma unroll
        for (int g = 0; g < 4; g++) {
            float4 v = lds128v(hrd_e + (unsigned)(g * 16));
            h_all[3 * g + 0] = v.x; h_all[3 * g + 1] = v.y; h_all[3 * g + 2] = v.z;
        }
        float o1[H_DIM], o2[H_DIM];
        #pragma unroll
        for (int j = 0; j < H_DIM; j++) {
            float s = sb1[j];
            #pragma unroll
            for (int k = 0; k < H_DIM; k++) s = fmaf(sW1[j * H_DIM + k], h_all[k], s);
            o1[j] = fmaxf(s, 0.0f);
        }
        #pragma unroll
        for (int j = 0; j < H_DIM; j++) {
            float s = sb2[j];
            #pragma unroll
            for (int k = 0; k < H_DIM; k++) s = fmaf(sW2[j * H_DIM + k], o1[k], s);
            o2[j] = fmaxf(s, 0.0f);
        }
        float s = sb3[0];
        #pragma unroll
        for (int k = 0; k < H_DIM; k++) s = fmaf(sW3[k], o2[k], s);
        out[b] = s;
    }
}

extern "C" void kernel_launch(void* const* d_in, const int* in_sizes, int n_in,
                              void* d_out, int out_size) {
    (void)in_sizes; (void)n_in; (void)out_size;
    const float* x    = (const float*)d_in[0];
    const float* W_ih = (const float*)d_in[1];
    const float* b_ih = (const float*)d_in[2];
    const float* W_hh = (const float*)d_in[3];
    const float* b_hh = (const float*)d_in[4];
    const float* W1   = (const float*)d_in[5];
    const float* b1   = (const float*)d_in[6];
    const float* W2   = (const float*)d_in[7];
    const float* b2   = (const float*)d_in[8];
    const float* W3   = (const float*)d_in[9];
    const float* b3   = (const float*)d_in[10];
    float* out = (float*)d_out;

    cudaFuncSetAttribute(rnn_fused_kernel,
                         cudaFuncAttributeMaxDynamicSharedMemorySize, SMEM_BYTES);

    dim3 grid(B_TOT / EPB);   // 512 blocks of 2 independent warps
    dim3 block(NTHREADS);     // 64 threads
    rnn_fused_kernel<<<grid, block, SMEM_BYTES>>>(
        x, W_ih, b_ih, W_hh, b_hh, W1, b1, W2, b2, W3, b3, out);
}

// round 17
// speedup vs baseline: 1.2934x; 1.2934x over previous
#include <cuda_runtime.h>

#define B_TOT    8192
#define T_LEN    512
#define F_IN     24
#define H_DIM    12
#define CHUNK    8
#define ELEMS    32               // elements per block
#define NTHREADS 256              // 4 consumer warps + 4 producer warps
#define NCHUNK   (T_LEN / CHUNK)  // 64
#define XROW     28               // x row stride (floats): tt-major rows conflict-free
#define XS_FL    (CHUNK * ELEMS * XROW)   // 7168 floats per buffer
#define XP_FL    (CHUNK * ELEMS * 16)     // 4096 floats per buffer
#define SMEM_BYTES ((2 * XS_FL + 2 * XP_FL) * 4)   // 90112 B
#define SCALE_T  2.885390082f     // 2*log2(e)

typedef unsigned long long u64;

__device__ __forceinline__ unsigned smem_u32(const void* p) {
    return (unsigned)__cvta_generic_to_shared(p);
}
__device__ __forceinline__ void cp_async16(unsigned dst, const void* src) {
    asm volatile("cp.async.cg.shared.global [%0], [%1], 16;\n" :: "r"(dst), "l"(src));
}
__device__ __forceinline__ void cp_commit() {
    asm volatile("cp.async.commit_group;\n" ::: "memory");
}
template <int N> __device__ __forceinline__ void cp_wait() {
    asm volatile("cp.async.wait_group %0;\n" :: "n"(N) : "memory");
}

__device__ __forceinline__ u64 pack2(float lo, float hi) {
    u64 d; asm("mov.b64 %0, {%1, %2};" : "=l"(d) : "f"(lo), "f"(hi)); return d;
}
__device__ __forceinline__ void unpack2(u64 d, float& lo, float& hi) {
    asm("mov.b64 {%0, %1}, %2;" : "=f"(lo), "=f"(hi) : "l"(d));
}
__device__ __forceinline__ u64 fma2(u64 a, u64 b, u64 c) {
    u64 d; asm("fma.rn.f32x2 %0, %1, %2, %3;" : "=l"(d) : "l"(a), "l"(b), "l"(c)); return d;
}
__device__ __forceinline__ u64 add2(u64 a, u64 b) {
    u64 d; asm("add.rn.f32x2 %0, %1, %2;" : "=l"(d) : "l"(a), "l"(b)); return d;
}
__device__ __forceinline__ float hadd2(u64 a) {
    float lo, hi; unpack2(a, lo, hi); return lo + hi;
}

// tanh on PRESCALED input: sx = 2*log2(e)*x -> tanh(x) = 1 - 2*rcp(2^sx + 1).
__device__ __forceinline__ float tanh_prescaled(float sx) {
    float e;
    asm("ex2.approx.f32 %0, %1;" : "=f"(e) : "f"(sx));
    float r;
    asm("rcp.approx.f32 %0, %1;" : "=f"(r) : "f"(e + 1.0f));
    return fmaf(-2.0f, r, 1.0f);
}

__global__ void __launch_bounds__(NTHREADS) rnn_ws_kernel(
    const float* __restrict__ x,
    const float* __restrict__ W_ih, const float* __restrict__ b_ih,
    const float* __restrict__ W_hh, const float* __restrict__ b_hh,
    const float* __restrict__ W1,   const float* __restrict__ b1,
    const float* __restrict__ W2,   const float* __restrict__ b2,
    const float* __restrict__ W3,   const float* __restrict__ b3,
    float* __restrict__ out)
{
    extern __shared__ float sm[];
    float* xs = sm;                 // [2][CHUNK*ELEMS][XROW], row = tt*ELEMS + e
    float* xp = sm + 2 * XS_FL;     // [2][CHUNK*ELEMS][16],  item = tt*ELEMS + e
    __shared__ float sW1[144], sW2[144], sb1[12], sb2[12], sW3[12], sb3[1];

    const int tid  = threadIdx.x;
    const int wid  = tid >> 5;
    const int lane = tid & 31;
    const int b0   = blockIdx.x * ELEMS;

    // MLP weights (tiny; all threads cooperate; first bar orders use)
    for (int i = tid; i < 144; i += NTHREADS) { sW1[i] = W1[i]; sW2[i] = W2[i]; }
    if (tid < 12) { sb1[tid] = b1[tid]; sb2[tid] = b2[tid]; sW3[tid] = W3[tid]; }
    if (tid == 0) sb3[0] = b3[0];

    if (wid < 4) {
        // ===================== CONSUMERS: serial recurrence =====================
        const int e    = wid * 8 + (lane >> 2);   // element 0..31
        const int sub  = lane & 3;                // 3 h-rows per thread
        const int j0   = sub * 3;
        const int qbase = lane & ~3;
        const int b    = b0 + e;

        u64 whh2[3][H_DIM / 2];
        #pragma unroll
        for (int c = 0; c < 3; c++) {
            const int j = j0 + c;
            #pragma unroll
            for (int p = 0; p < H_DIM / 2; p++)
                whh2[c][p] = pack2(SCALE_T * W_hh[j * H_DIM + 2 * p],
                                   SCALE_T * W_hh[j * H_DIM + 2 * p + 1]);
        }

        u64 hp[H_DIM / 2];
        #pragma unroll
        for (int k = 0; k < H_DIM / 2; k++) hp[k] = 0ull;
        const u64 ZERO2 = 0ull;

        __syncthreads();   // BAR1 (x chunks 0,1 landed)
        __syncthreads();   // BAR2 (xp chunk 0 ready)

        for (int c = 0; c < NCHUNK; c++) {
            const float* xpb = xp + (c & 1) * XP_FL;
            #pragma unroll
            for (int tt = 0; tt < CHUNK; tt++) {
                // xp for this thread's 3 rows: one conflict-free LDS.128
                float4 v = *(const float4*)(xpb + (tt * ELEMS + e) * 16 + sub * 4);

                u64 sA0 = fma2(whh2[0][0], hp[0], pack2(v.x, 0.0f));
                u64 sA1 = fma2(whh2[1][0], hp[0], pack2(v.y, 0.0f));
                u64 sA2 = fma2(whh2[2][0], hp[0], pack2(v.z, 0.0f));
                u64 sB0 = fma2(whh2[0][3], hp[3], ZERO2);
                u64 sB1 = fma2(whh2[1][3], hp[3], ZERO2);
                u64 sB2 = fma2(whh2[2][3], hp[3], ZERO2);
                sA0 = fma2(whh2[0][1], hp[1], sA0);
                sA1 = fma2(whh2[1][1], hp[1], sA1);
                sA2 = fma2(whh2[2][1], hp[1], sA2);
                sB0 = fma2(whh2[0][4], hp[4], sB0);
                sB1 = fma2(whh2[1][4], hp[4], sB1);
                sB2 = fma2(whh2[2][4], hp[4], sB2);
                sA0 = fma2(whh2[0][2], hp[2], sA0);
                sA1 = fma2(whh2[1][2], hp[2], sA1);
                sA2 = fma2(whh2[2][2], hp[2], sA2);
                sB0 = fma2(whh2[0][5], hp[5], sB0);
                sB1 = fma2(whh2[1][5], hp[5], sB1);
                sB2 = fma2(whh2[2][5], hp[5], sB2);

                float hl0 = tanh_prescaled(hadd2(add2(sA0, sB0)));
                float hl1 = tanh_prescaled(hadd2(add2(sA1, sB1)));
                float hl2 = tanh_prescaled(hadd2(add2(sA2, sB2)));

                float hs[H_DIM];
                #pragma unroll
                for (int s = 0; s < 4; s++) {
                    hs[s * 3 + 0] = __shfl_sync(0xffffffffu, hl0, qbase + s);
                    hs[s * 3 + 1] = __shfl_sync(0xffffffffu, hl1, qbase + s);
                    hs[s * 3 + 2] = __shfl_sync(0xffffffffu, hl2, qbase + s);
                }
                #pragma unroll
                for (int p = 0; p < H_DIM / 2; p++)
                    hp[p] = pack2(hs[2 * p], hs[2 * p + 1]);
            }
            __syncthreads();   // chunk boundary (matched by producers)
        }

        // MLP head
        if (sub == 0) {
            float h_all[H_DIM];
            #pragma unroll
            for (int p = 0; p < H_DIM / 2; p++) unpack2(hp[p], h_all[2 * p], h_all[2 * p + 1]);
            float o1[H_DIM], o2[H_DIM];
            #pragma unroll
            for (int j = 0; j < H_DIM; j++) {
                float s = sb1[j];
                #pragma unroll
                for (int k = 0; k < H_DIM; k++) s = fmaf(sW1[j * H_DIM + k], h_all[k], s);
                o1[j] = fmaxf(s, 0.0f);
            }
            #pragma unroll
            for (int j = 0; j < H_DIM; j++) {
                float s = sb2[j];
                #pragma unroll
                for (int k = 0; k < H_DIM; k++) s = fmaf(sW2[j * H_DIM + k], o1[k], s);
                o2[j] = fmaxf(s, 0.0f);
            }
            float s = sb3[0];
            #pragma unroll
            for (int k = 0; k < H_DIM; k++) s = fmaf(sW3[k], o2[k], s);
            out[b] = s;
        }
    } else {
        // ===================== PRODUCERS: input projection =====================
        const int q    = (wid - 4) * 32 + lane;   // 0..127
        const int sub  = q & 3;                   // 3 output rows per lane
        const int slot = q >> 2;                  // element this lane projects (0..31)
        const int j0   = sub * 3;

        u64 wih2[3][F_IN / 2];
        float bias[3];
        #pragma unroll
        for (int c = 0; c < 3; c++) {
            const int j = j0 + c;
            #pragma unroll
            for (int p = 0; p < F_IN / 2; p++)
                wih2[c][p] = pack2(SCALE_T * W_ih[j * F_IN + 2 * p],
                                   SCALE_T * W_ih[j * F_IN + 2 * p + 1]);
            bias[c] = SCALE_T * (b_ih[j] + b_hh[j]);
        }

        // x loader: lane q stages rows (e=q>>3, tt=q&7) and (e=16+(q>>3), tt=q&7),
        // stored tt-major at row tt*ELEMS+e (96B each, gmem-coalesced by quad).
        const int le = q >> 3, ltt = q & 7;
        const float* gA = x + ((long)(b0 + le) * T_LEN + ltt) * F_IN;
        const float* gB = gA + (long)16 * T_LEN * F_IN;
        const unsigned xsb = smem_u32(xs);
        const unsigned dA0 = xsb + (unsigned)(((ltt * ELEMS + le) * XROW) * 4);
        const unsigned dB0 = dA0 + (unsigned)(16 * XROW * 4);

        auto load_x = [&](int buf, int c) {
            const long off = (long)c * (CHUNK * F_IN);
            const unsigned boff = (unsigned)buf * (XS_FL * 4);
            #pragma unroll
            for (int qq = 0; qq < 6; qq++) {
                cp_async16(dA0 + boff + (unsigned)(qq * 16), gA + off + qq * 4);
                cp_async16(dB0 + boff + (unsigned)(qq * 16), gB + off + qq * 4);
            }
            cp_commit();
        };

        // projection of one chunk: lane handles its elem (slot) for tt=0..7
        auto compute_xp = [&](int srcbuf, int dstbuf) {
            const float* xb = xs + srcbuf * XS_FL;
            float* xpd = xp + dstbuf * XP_FL;
            #pragma unroll
            for (int i = 0; i < CHUNK; i++) {
                const ulonglong2* xr = (const ulonglong2*)(xb + (i * ELEMS + slot) * XROW);
                u64 a0 = 0ull, a1 = 0ull, a2 = 0ull;
                #pragma unroll
                for (int qq = 0; qq < 6; qq++) {
                    ulonglong2 v = xr[qq];
                    a0 = fma2(wih2[0][2 * qq + 0], v.x, a0);
                    a1 = fma2(wih2[1][2 * qq + 0], v.x, a1);
                    a2 = fma2(wih2[2][2 * qq + 0], v.x, a2);
                    a0 = fma2(wih2[0][2 * qq + 1], v.y, a0);
                    a1 = fma2(wih2[1][2 * qq + 1], v.y, a1);
                    a2 = fma2(wih2[2][2 * qq + 1], v.y, a2);
                }
                float4 r;
                r.x = hadd2(a0) + bias[0];
                r.y = hadd2(a1) + bias[1];
                r.z = hadd2(a2) + bias[2];
                r.w = 0.0f;
                *(float4*)(xpd + (i * ELEMS + slot) * 16 + sub * 4) = r;  // STS.128
            }
        };

        // prologue: chunks 0 and 1 staged; xp chunk 0 built
        load_x(0, 0);
        load_x(1, 1);
        cp_wait<0>();
        __syncthreads();   // BAR1: all producer warps' x data visible
        compute_xp(0, 0);
        __syncthreads();   // BAR2: xp chunk 0 visible to consumers

        for (int c = 0; c < NCHUNK; c++) {
            if (c + 1 < NCHUNK) {
                if (c + 2 < NCHUNK) load_x(c & 1, c + 2);  // overwrite dead chunk-c x
                compute_xp((c + 1) & 1, (c + 1) & 1);      // overlaps in-flight load
                cp_wait<0>();                              // chunk c+2 landed
            }
            __syncthreads();   // chunk boundary (matched by consumers)
        }
    }
}

extern "C" void kernel_launch(void* const* d_in, const int* in_sizes, int n_in,
                              void* d_out, int out_size) {
    (void)in_sizes; (void)n_in; (void)out_size;
    const float* x    = (const float*)d_in[0];
    const float* W_ih = (const float*)d_in[1];
    const float* b_ih = (const float*)d_in[2];
    const float* W_hh = (const float*)d_in[3];
    const float* b_hh = (const float*)d_in[4];
    const float* W1   = (const float*)d_in[5];
    const float* b1   = (const float*)d_in[6];
    const float* W2   = (const float*)d_in[7];
    const float* b2   = (const float*)d_in[8];
    const float* W3   = (const float*)d_in[9];
    const float* b3   = (const float*)d_in[10];
    float* out = (float*)d_out;

    cudaFuncSetAttribute(rnn_ws_kernel,
                         cudaFuncAttributeMaxDynamicSharedMemorySize, SMEM_BYTES);

    dim3 grid(B_TOT / ELEMS);   // 256 blocks
    dim3 block(NTHREADS);       // 256 threads: 4 consumer + 4 producer warps
    rnn_ws_kernel<<<grid, block, SMEM_BYTES>>>(
        x, W_ih, b_ih, W_hh, b_hh, W1, b1, W2, b2, W3, b3, out);
}